// round 5
// baseline (speedup 1.0000x reference)
#include <cuda_runtime.h>
#include <cuda_bf16.h>

// ---------------------------------------------------------------------------
// DIN forward, fp32, f32x2 FMA.
//  Kernel A: attention scores, t-split (2 CTAs per b, 2 CTAs/SM) -> g_scores
//  Kernel B: softmax + interest (re-gather keys from L2)         -> g_interest
//  Kernel C: final MLP, K-split partials                          -> d_out
// ---------------------------------------------------------------------------

#define B_ROWS 4096
#define T_LEN  200
#define TPAD   224
#define THALF  112          // t's per kernel-A CTA (14 warps * 8)
#define E_DIM  64
#define NTHRA  448

__device__ float g_scores[B_ROWS * TPAD];
__device__ float g_interest[B_ROWS * E_DIM];

__device__ __forceinline__ float2 fma2(float2 a, float2 b, float2 c) {
    float2 d;
    asm("fma.rn.f32x2 %0, %1, %2, %3;"
        : "=l"(*(unsigned long long*)&d)
        : "l"(*(unsigned long long*)&a),
          "l"(*(unsigned long long*)&b),
          "l"(*(unsigned long long*)&c));
    return d;
}

// ---- kernel A smem layout (float offsets) ----
#define A_XT    0                  // 64 x 112 = 7168
#define A_W12   7168               // 64 x 64  = 4096
#define A_H1    11264              // 64 x 116 = 7424
#define A_W2    18688              // 64 x 32  = 2048
#define A_Q     20736              // 64
#define A_QC    20800              // 64
#define SMEMA_BYTES (20864 * 4)    // 83456 B -> 2 CTAs/SM

__global__ void __launch_bounds__(NTHRA, 2)
din_scores_kernel(const int* __restrict__ tgt,
                  const int* __restrict__ hist,
                  const int* __restrict__ mask,        // bool as int32
                  const float* __restrict__ item_table,
                  const float* __restrict__ w1, const float* __restrict__ b1,
                  const float* __restrict__ w2, const float* __restrict__ b2,
                  const float* __restrict__ wo, const float* __restrict__ bo)
{
    extern __shared__ float sm[];
    float* XT  = sm + A_XT;
    float* W12 = sm + A_W12;
    float* H1  = sm + A_H1;
    float* W2s = sm + A_W2;
    float* Q   = sm + A_Q;
    float* QC  = sm + A_QC;

    const int b    = blockIdx.x >> 1;
    const int t0   = (blockIdx.x & 1) * THALF;
    const int tid  = threadIdx.x;
    const int lane = tid & 31;
    const int warp = tid >> 5;

    // ---- phase 0: q, W2, gather keys transposed XT[e][t_local] ----
    if (tid < E_DIM) Q[tid] = item_table[(long)tgt[b] * E_DIM + tid];
    for (int i = tid; i < 64 * 32; i += NTHRA) W2s[i] = w2[i];

    for (int i = tid; i < 16 * THALF; i += NTHRA) {
        int t = i % THALF;
        int f = i / THALF;
        int tg = t0 + t;
        float4 v = make_float4(0.f, 0.f, 0.f, 0.f);
        if (tg < T_LEN) {
            int row = hist[b * T_LEN + tg];
            v = *(const float4*)(item_table + (long)row * E_DIM + 4 * f);
        }
        XT[(4 * f + 0) * THALF + t] = v.x;
        XT[(4 * f + 1) * THALF + t] = v.y;
        XT[(4 * f + 2) * THALF + t] = v.z;
        XT[(4 * f + 3) * THALF + t] = v.w;
    }
    __syncthreads();

    // ---- phase 1: fold weights ----
    for (int i = tid; i < 4096; i += NTHRA) {
        int k = i >> 6;
        W12[i] = w1[i] + w1[8192 + i] + Q[k] * w1[12288 + i];
    }
    if (tid < E_DIM) {
        float s = b1[tid];
        #pragma unroll 8
        for (int e = 0; e < 64; ++e)
            s += Q[e] * (w1[4096 + e * 64 + tid] - w1[8192 + e * 64 + tid]);
        QC[tid] = s;
    }
    __syncthreads();

    // ---- GEMM1: warp owns m in [8w, 8w+8), lane owns j = {lane, lane+32} ----
    const int mb = warp * 8;
    float2 acc0[4], acc1[4];
    #pragma unroll
    for (int p = 0; p < 4; ++p) { acc0[p] = make_float2(0.f, 0.f); acc1[p] = make_float2(0.f, 0.f); }

    #pragma unroll 4
    for (int k = 0; k < 64; ++k) {
        float b0s = W12[k * 64 + lane];
        float b1s = W12[k * 64 + lane + 32];
        float2 bb0 = make_float2(b0s, b0s);
        float2 bb1 = make_float2(b1s, b1s);
        const float4* xr4 = (const float4*)(XT + k * THALF + mb);
        float4 aA = xr4[0];
        float4 aB = xr4[1];
        acc0[0] = fma2(make_float2(aA.x, aA.y), bb0, acc0[0]);
        acc1[0] = fma2(make_float2(aA.x, aA.y), bb1, acc1[0]);
        acc0[1] = fma2(make_float2(aA.z, aA.w), bb0, acc0[1]);
        acc1[1] = fma2(make_float2(aA.z, aA.w), bb1, acc1[1]);
        acc0[2] = fma2(make_float2(aB.x, aB.y), bb0, acc0[2]);
        acc1[2] = fma2(make_float2(aB.x, aB.y), bb1, acc1[2]);
        acc0[3] = fma2(make_float2(aB.z, aB.w), bb0, acc0[3]);
        acc1[3] = fma2(make_float2(aB.z, aB.w), bb1, acc1[3]);
    }
    {
        float qa = QC[lane], qb = QC[lane + 32];
        #pragma unroll
        for (int p = 0; p < 4; ++p) {
            float2 r0 = make_float2(fmaxf(acc0[p].x + qa, 0.f), fmaxf(acc0[p].y + qa, 0.f));
            float2 r1 = make_float2(fmaxf(acc1[p].x + qb, 0.f), fmaxf(acc1[p].y + qb, 0.f));
            *(float2*)(H1 + lane * 116 + mb + 2 * p)        = r0;
            *(float2*)(H1 + (lane + 32) * 116 + mb + 2 * p) = r1;
        }
    }
    // H1 for this warp's m-range is produced entirely within this warp.
    __syncwarp();

    // ---- GEMM2 (64->32) + score write ----
    float2 acc[4];
    #pragma unroll
    for (int p = 0; p < 4; ++p) acc[p] = make_float2(0.f, 0.f);

    #pragma unroll 4
    for (int k = 0; k < 64; ++k) {
        float bs = W2s[k * 32 + lane];
        float2 bb = make_float2(bs, bs);
        const float4* hr4 = (const float4*)(H1 + k * 116 + mb);
        float4 aA = hr4[0];
        float4 aB = hr4[1];
        acc[0] = fma2(make_float2(aA.x, aA.y), bb, acc[0]);
        acc[1] = fma2(make_float2(aA.z, aA.w), bb, acc[1]);
        acc[2] = fma2(make_float2(aB.x, aB.y), bb, acc[2]);
        acc[3] = fma2(make_float2(aB.z, aB.w), bb, acc[3]);
    }
    {
        float bb2 = b2[lane];
        float wol = wo[lane];
        float bos = bo[0];
        #pragma unroll
        for (int p = 0; p < 4; ++p) {
            float hx = fmaxf(acc[p].x + bb2, 0.f) * wol;
            float hy = fmaxf(acc[p].y + bb2, 0.f) * wol;
            #pragma unroll
            for (int off = 16; off > 0; off >>= 1) {
                hx += __shfl_xor_sync(0xffffffffu, hx, off);
                hy += __shfl_xor_sync(0xffffffffu, hy, off);
            }
            if (lane == 0) {
                int tg0 = t0 + mb + 2 * p;
                int m0  = (tg0     < T_LEN) ? mask[b * T_LEN + tg0]     : 0;
                int m1  = (tg0 + 1 < T_LEN) ? mask[b * T_LEN + tg0 + 1] : 0;
                g_scores[b * TPAD + tg0]     = m0 ? hx + bos : -1e9f;
                g_scores[b * TPAD + tg0 + 1] = m1 ? hy + bos : -1e9f;
            }
        }
    }
}

// ---------------------------------------------------------------------------
// Kernel B: softmax over 224 scores + interest vector (re-gather keys).
// 256 threads, 8 warps; warp w owns e-slice [8w, 8w+8).
// ---------------------------------------------------------------------------
__global__ void __launch_bounds__(256, 8)
din_softmax_kernel(const int* __restrict__ hist,
                   const float* __restrict__ item_table)
{
    __shared__ float SC[TPAD];
    __shared__ float WG[TPAD];
    __shared__ float RED[8];
    __shared__ float SV[2];

    const int b    = blockIdx.x;
    const int tid  = threadIdx.x;
    const int lane = tid & 31;
    const int warp = tid >> 5;

    float s = (tid < TPAD) ? g_scores[b * TPAD + tid] : -3.4e38f;
    if (tid < TPAD) SC[tid] = s;

    // max
    float m = s;
    #pragma unroll
    for (int off = 16; off > 0; off >>= 1)
        m = fmaxf(m, __shfl_xor_sync(0xffffffffu, m, off));
    if (lane == 0) RED[warp] = m;
    __syncthreads();
    if (warp == 0) {
        float mm = (lane < 7) ? RED[lane] : -3.4e38f;
        #pragma unroll
        for (int off = 4; off > 0; off >>= 1)
            mm = fmaxf(mm, __shfl_xor_sync(0xffffffffu, mm, off));
        if (lane == 0) SV[0] = mm;
    }
    __syncthreads();

    // exp + sum
    float e = 0.f;
    if (tid < TPAD) {
        e = expf(SC[tid] - SV[0]);
        WG[tid] = e;
    }
    #pragma unroll
    for (int off = 16; off > 0; off >>= 1)
        e += __shfl_xor_sync(0xffffffffu, e, off);
    if (lane == 0) RED[warp] = e;
    __syncthreads();
    if (warp == 0) {
        float t2 = (lane < 7) ? RED[lane] : 0.f;
        #pragma unroll
        for (int off = 4; off > 0; off >>= 1)
            t2 += __shfl_xor_sync(0xffffffffu, t2, off);
        if (lane == 0) SV[1] = t2;
    }
    __syncthreads();

    // interest: warp owns 8 e's, lanes walk t
    const int e0 = warp * 8;
    float a0=0.f,a1=0.f,a2=0.f,a3=0.f,a4=0.f,a5=0.f,a6=0.f,a7=0.f;
    #pragma unroll
    for (int i = 0; i < 7; ++i) {
        int t = lane + 32 * i;
        float wv = WG[t];
        if (t < T_LEN) {
            int row = hist[b * T_LEN + t];
            const float* kp = item_table + (long)row * E_DIM + e0;
            float4 va = *(const float4*)(kp);
            float4 vb = *(const float4*)(kp + 4);
            a0 += wv * va.x; a1 += wv * va.y; a2 += wv * va.z; a3 += wv * va.w;
            a4 += wv * vb.x; a5 += wv * vb.y; a6 += wv * vb.z; a7 += wv * vb.w;
        }
    }
    #pragma unroll
    for (int off = 16; off > 0; off >>= 1) {
        a0 += __shfl_xor_sync(0xffffffffu, a0, off);
        a1 += __shfl_xor_sync(0xffffffffu, a1, off);
        a2 += __shfl_xor_sync(0xffffffffu, a2, off);
        a3 += __shfl_xor_sync(0xffffffffu, a3, off);
        a4 += __shfl_xor_sync(0xffffffffu, a4, off);
        a5 += __shfl_xor_sync(0xffffffffu, a5, off);
        a6 += __shfl_xor_sync(0xffffffffu, a6, off);
        a7 += __shfl_xor_sync(0xffffffffu, a7, off);
    }
    if (lane == 0) {
        float invs = 1.0f / SV[1];
        float* gi = g_interest + (long)b * E_DIM + e0;
        gi[0]=a0*invs; gi[1]=a1*invs; gi[2]=a2*invs; gi[3]=a3*invs;
        gi[4]=a4*invs; gi[5]=a5*invs; gi[6]=a6*invs; gi[7]=a7*invs;
    }
}

// ---------------------------------------------------------------------------
// Kernel C: final MLP, 8 rows/CTA, 512 threads, K-split partials.
// ---------------------------------------------------------------------------
#define BTILE 8
#define C_AT   0                        // 272 x 8     = 2176
#define C_P    2176                     // 512 x 10    = 5120
#define C_H1   (2176 + 5120)            // 256 x 12    = 3072
#define C_Q    (2176 + 5120 + 3072)     // 512 x 10    = 5120
#define C_R    (2176 + 5120 + 3072 + 5120) // 32
#define SMEMC_BYTES ((2176 + 5120 + 3072 + 5120 + 32) * 4)

__global__ void __launch_bounds__(512, 2)
din_mlp_kernel(const int* __restrict__ tgt,
               const int* __restrict__ sf,
               const float* __restrict__ dense,
               const float* __restrict__ item_table,
               const float* __restrict__ user_table,
               const float* __restrict__ ctx_table,
               const float* __restrict__ w1, const float* __restrict__ b1,
               const float* __restrict__ w2, const float* __restrict__ b2,
               const float* __restrict__ ow, const float* __restrict__ ob,
               float* __restrict__ out)
{
    extern __shared__ float sm[];
    float* At  = sm + C_AT;
    float* P   = sm + C_P;
    float* H1t = sm + C_H1;
    float* Qp  = sm + C_Q;
    float* R   = sm + C_R;

    const int b0   = blockIdx.x * BTILE;
    const int tid  = threadIdx.x;
    const int lane = tid & 31;

    // build transposed feature tile At[k][b]
    for (int i = tid; i < 272 * BTILE; i += 512) {
        int bb = i & (BTILE - 1);
        int k  = i / BTILE;
        int gb = b0 + bb;
        float v;
        if (k < 64)        v = user_table[(long)sf[gb * 2] * 64 + k];
        else if (k < 128)  v = ctx_table[(long)sf[gb * 2 + 1] * 64 + (k - 64)];
        else if (k < 192)  v = item_table[(long)tgt[gb] * 64 + (k - 128)];
        else if (k < 256)  v = g_interest[(long)gb * 64 + (k - 192)];
        else               v = dense[gb * 16 + (k - 256)];
        At[k * BTILE + bb] = v;
    }
    __syncthreads();

    // layer 1: 272 -> 256, K split by 2 (thread = channel n, half ks)
    {
        const int n  = tid & 255;
        const int ks = tid >> 8;
        const int k0 = ks * 136;
        float2 acc[4];
        #pragma unroll
        for (int p = 0; p < 4; ++p) acc[p] = make_float2(0.f, 0.f);
        #pragma unroll 4
        for (int k = k0; k < k0 + 136; ++k) {
            float wv = w1[k * 256 + n];
            float2 bb = make_float2(wv, wv);
            const float4* ar4 = (const float4*)(At + k * BTILE);
            float4 aA = ar4[0];
            float4 aB = ar4[1];
            acc[0] = fma2(make_float2(aA.x, aA.y), bb, acc[0]);
            acc[1] = fma2(make_float2(aA.z, aA.w), bb, acc[1]);
            acc[2] = fma2(make_float2(aB.x, aB.y), bb, acc[2]);
            acc[3] = fma2(make_float2(aB.z, aB.w), bb, acc[3]);
        }
        float* pr = P + tid * 10;
        #pragma unroll
        for (int p = 0; p < 4; ++p) *(float2*)(pr + 2 * p) = acc[p];
    }
    __syncthreads();

    // combine layer-1 partials -> H1t[n][m], relu
    if (tid < 256) {
        float bias = b1[tid];
        const float* p0 = P + tid * 10;
        const float* p1 = P + (tid + 256) * 10;
        #pragma unroll
        for (int p = 0; p < 4; ++p) {
            float2 x = *(const float2*)(p0 + 2 * p);
            float2 y = *(const float2*)(p1 + 2 * p);
            float2 r = make_float2(fmaxf(x.x + y.x + bias, 0.f),
                                   fmaxf(x.y + y.y + bias, 0.f));
            *(float2*)(H1t + tid * 12 + 2 * p) = r;
        }
    }
    __syncthreads();

    // layer 2: 256 -> 128, K split by 4 (thread = channel n, quarter ks)
    {
        const int n  = tid & 127;
        const int ks = tid >> 7;
        const int k0 = ks * 64;
        float2 acc[4];
        #pragma unroll
        for (int p = 0; p < 4; ++p) acc[p] = make_float2(0.f, 0.f);
        #pragma unroll 4
        for (int k = k0; k < k0 + 64; ++k) {
            float wv = w2[k * 128 + n];
            float2 bb = make_float2(wv, wv);
            const float4* hr4 = (const float4*)(H1t + k * 12);
            float4 aA = hr4[0];
            float4 aB = hr4[1];
            acc[0] = fma2(make_float2(aA.x, aA.y), bb, acc[0]);
            acc[1] = fma2(make_float2(aA.z, aA.w), bb, acc[1]);
            acc[2] = fma2(make_float2(aB.x, aB.y), bb, acc[2]);
            acc[3] = fma2(make_float2(aB.z, aB.w), bb, acc[3]);
        }
        float* qr = Qp + tid * 10;
        #pragma unroll
        for (int p = 0; p < 4; ++p) *(float2*)(qr + 2 * p) = acc[p];
    }
    __syncthreads();

    // combine layer-2 partials, relu, *ow, reduce over channels
    if (tid < 128) {
        const int n = tid;
        float bias = b2[n];
        float owl  = ow[n];
        float s[8];
        #pragma unroll
        for (int m = 0; m < 8; ++m) {
            float v = Qp[(n)       * 10 + m]
                    + Qp[(n + 128) * 10 + m]
                    + Qp[(n + 256) * 10 + m]
                    + Qp[(n + 384) * 10 + m];
            s[m] = fmaxf(v + bias, 0.f) * owl;
        }
        #pragma unroll
        for (int off = 16; off > 0; off >>= 1) {
            #pragma unroll
            for (int m = 0; m < 8; ++m)
                s[m] += __shfl_xor_sync(0xffffffffu, s[m], off);
        }
        if (lane == 0) {
            int w = tid >> 5;
            #pragma unroll
            for (int m = 0; m < 8; ++m) R[w * 8 + m] = s[m];
        }
    }
    __syncthreads();
    if (tid < BTILE) {
        float s = R[tid] + R[8 + tid] + R[16 + tid] + R[24 + tid] + ob[0];
        out[b0 + tid] = s;
    }
}

// ---------------------------------------------------------------------------
extern "C" void kernel_launch(void* const* d_in, const int* in_sizes, int n_in,
                              void* d_out, int out_size)
{
    const int*           tgt   = (const int*)d_in[0];
    const int*           hist  = (const int*)d_in[1];
    const int*           mask  = (const int*)d_in[2];   // bool -> int32
    const int*           sf    = (const int*)d_in[3];
    const float*         dense = (const float*)d_in[4];
    const float*         item_table = (const float*)d_in[5];
    const float*         user_table = (const float*)d_in[6];
    const float*         ctx_table  = (const float*)d_in[7];
    const float*         att_w1 = (const float*)d_in[8];
    const float*         att_b1 = (const float*)d_in[9];
    const float*         att_w2 = (const float*)d_in[10];
    const float*         att_b2 = (const float*)d_in[11];
    const float*         att_wo = (const float*)d_in[12];
    const float*         att_bo = (const float*)d_in[13];
    const float*         mlp_w1 = (const float*)d_in[14];
    const float*         mlp_b1 = (const float*)d_in[15];
    const float*         mlp_w2 = (const float*)d_in[16];
    const float*         mlp_b2 = (const float*)d_in[17];
    const float*         out_w  = (const float*)d_in[18];
    const float*         out_b  = (const float*)d_in[19];
    float*               out    = (float*)d_out;

    cudaFuncSetAttribute(din_scores_kernel, cudaFuncAttributeMaxDynamicSharedMemorySize, SMEMA_BYTES);
    cudaFuncSetAttribute(din_mlp_kernel,    cudaFuncAttributeMaxDynamicSharedMemorySize, SMEMC_BYTES);

    din_scores_kernel<<<B_ROWS * 2, NTHRA, SMEMA_BYTES>>>(
        tgt, hist, mask, item_table,
        att_w1, att_b1, att_w2, att_b2, att_wo, att_bo);

    din_softmax_kernel<<<B_ROWS, 256>>>(hist, item_table);

    din_mlp_kernel<<<B_ROWS / BTILE, 512, SMEMC_BYTES>>>(
        tgt, sf, dense, item_table, user_table, ctx_table,
        mlp_w1, mlp_b1, mlp_w2, mlp_b2, out_w, out_b, out);
}

// round 7
// speedup vs baseline: 1.0798x; 1.0798x over previous
#include <cuda_runtime.h>
#include <cuda_bf16.h>
#include <cstdint>

// ---------------------------------------------------------------------------
// DIN forward.
//  Kernel F: fold per-b attention weights -> g_w12t[b][j][k], g_qc[b][j]
//  Kernel A: scores via mma.sync tf32 (3xTF32 split for fp32-like accuracy)
//  Kernel B: softmax + interest
//  Kernel C: final MLP (fp32, k-split)
// ---------------------------------------------------------------------------

#define B_ROWS 4096
#define T_LEN  200
#define TPAD   224
#define E_DIM  64

__device__ float g_w12t[B_ROWS * 64 * 64];   // [b][j][k]
__device__ float g_qc[B_ROWS * 64];
__device__ float g_scores[B_ROWS * TPAD];
__device__ float g_interest[B_ROWS * E_DIM];

__device__ __forceinline__ float2 fma2(float2 a, float2 b, float2 c) {
    float2 d;
    asm("fma.rn.f32x2 %0, %1, %2, %3;"
        : "=l"(*(unsigned long long*)&d)
        : "l"(*(unsigned long long*)&a),
          "l"(*(unsigned long long*)&b),
          "l"(*(unsigned long long*)&c));
    return d;
}

__device__ __forceinline__ uint32_t f2tf32(float f) {
    uint32_t u;
    asm("cvt.rna.tf32.f32 %0, %1;" : "=r"(u) : "f"(f));
    return u;
}
__device__ __forceinline__ void split3(float x, uint32_t& hi, uint32_t& lo) {
    hi = f2tf32(x);
    lo = f2tf32(x - __uint_as_float(hi));
}
// D += A*B  (m16n8k8, A row-major, B col-major, tf32 in, f32 acc)
__device__ __forceinline__ void mma168(float* d, const uint32_t* a, const uint32_t* b) {
    asm volatile(
        "mma.sync.aligned.m16n8k8.row.col.f32.tf32.tf32.f32 "
        "{%0,%1,%2,%3}, {%4,%5,%6,%7}, {%8,%9}, {%0,%1,%2,%3};"
        : "+f"(d[0]), "+f"(d[1]), "+f"(d[2]), "+f"(d[3])
        : "r"(a[0]), "r"(a[1]), "r"(a[2]), "r"(a[3]), "r"(b[0]), "r"(b[1]));
}

// ---------------------------------------------------------------------------
// Kernel F: fold weights per b, store transposed [j][k].
// ---------------------------------------------------------------------------
__global__ void __launch_bounds__(256, 4)
din_fold_kernel(const int* __restrict__ tgt,
                const float* __restrict__ item_table,
                const float* __restrict__ w1, const float* __restrict__ b1)
{
    __shared__ float Q[64];
    __shared__ float SM[64 * 65];
    const int b   = blockIdx.x;
    const int tid = threadIdx.x;

    if (tid < 64) Q[tid] = item_table[(long)tgt[b] * 64 + tid];
    __syncthreads();

    for (int i = tid; i < 4096; i += 256) {
        int k = i >> 6, j = i & 63;
        SM[k * 65 + j] = w1[i] + w1[8192 + i] + Q[k] * w1[12288 + i];
    }
    __syncthreads();
    for (int i = tid; i < 4096; i += 256) {
        int j = i >> 6, k = i & 63;
        g_w12t[(long)b * 4096 + i] = SM[k * 65 + j];
    }
    if (tid < 64) {
        float s = b1[tid];
        #pragma unroll 8
        for (int e = 0; e < 64; ++e)
            s += Q[e] * (w1[4096 + e * 64 + tid] - w1[8192 + e * 64 + tid]);
        g_qc[b * 64 + tid] = s;
    }
}

// ---------------------------------------------------------------------------
// Kernel A: scores via mma.sync tf32. grid = 2*B (two 128-t tiles per b).
// smem (fp32, padded stride 68):
//   KEYS[128][68] | H1[128][68] | W12T[64][68] | W2T[32][68] | QC | B2 | WO
// ---------------------------------------------------------------------------
#define SA_KEYS  0
#define SA_H1    8704
#define SA_W12T  17408
#define SA_W2T   21760
#define SA_QC    23936
#define SA_B2    24000
#define SA_WO    24032
#define SMEMA_FLOATS 24064
#define SMEMA_BYTES  (SMEMA_FLOATS * 4)

__global__ void __launch_bounds__(256, 2)
din_scores_kernel(const int* __restrict__ tgt,
                  const int* __restrict__ hist,
                  const int* __restrict__ mask,
                  const float* __restrict__ item_table,
                  const float* __restrict__ w2, const float* __restrict__ b2,
                  const float* __restrict__ wo, const float* __restrict__ bo)
{
    extern __shared__ float sm[];
    float* KEYS = sm + SA_KEYS;
    float* H1   = sm + SA_H1;
    float* W12T = sm + SA_W12T;
    float* W2T  = sm + SA_W2T;
    float* QC   = sm + SA_QC;
    float* B2S  = sm + SA_B2;
    float* WOS  = sm + SA_WO;

    const int b    = blockIdx.x >> 1;
    const int t0   = (blockIdx.x & 1) * 128;
    const int tid  = threadIdx.x;
    const int lane = tid & 31;
    const int wid  = tid >> 5;
    const int gid  = lane >> 2;     // 0..7
    const int tig  = lane & 3;      // 0..3

    // ---- stage operands ----
    // keys: KEYS[m][k], fp32
    for (int i = tid; i < 128 * 16; i += 256) {
        int f4 = i & 15;
        int m  = i >> 4;
        int tg = t0 + m;
        float4 v = make_float4(0.f, 0.f, 0.f, 0.f);
        if (tg < T_LEN) {
            int row = hist[b * T_LEN + tg];
            v = *(const float4*)(item_table + (long)row * E_DIM + 4 * f4);
        }
        *(float4*)(KEYS + m * 68 + 4 * f4) = v;
    }
    // W12T[j][k]
    for (int i = tid; i < 1024; i += 256) {
        float4 v = ((const float4*)(g_w12t + (long)b * 4096))[i];
        int j = i >> 4, kq = (i & 15) * 4;
        *(float4*)(W12T + j * 68 + kq) = v;
    }
    // W2T[n][k=j] from w2[j][n]
    for (int i = tid; i < 2048; i += 256) {
        int n = i & 31, j = i >> 5;
        W2T[n * 68 + j] = w2[i];
    }
    if (tid < 64) QC[tid] = g_qc[b * 64 + tid];
    if (tid < 32) { B2S[tid] = b2[tid]; WOS[tid] = wo[tid]; }
    __syncthreads();

    const int mb = wid * 16;

    // ---- GEMM1: H1[m][j] = relu(KEYS @ W12T^T + qc) ----
    {
        // preload A fragments (8 k-steps), split hi/lo
        uint32_t ahi[8][4], alo[8][4];
        #pragma unroll
        for (int ks = 0; ks < 8; ++ks) {
            float r0 = KEYS[(mb + gid)     * 68 + ks * 8 + tig];
            float r1 = KEYS[(mb + gid + 8) * 68 + ks * 8 + tig];
            float r2 = KEYS[(mb + gid)     * 68 + ks * 8 + tig + 4];
            float r3 = KEYS[(mb + gid + 8) * 68 + ks * 8 + tig + 4];
            split3(r0, ahi[ks][0], alo[ks][0]);
            split3(r1, ahi[ks][1], alo[ks][1]);
            split3(r2, ahi[ks][2], alo[ks][2]);
            split3(r3, ahi[ks][3], alo[ks][3]);
        }
        #pragma unroll
        for (int nt = 0; nt < 8; ++nt) {
            float acc[4] = {0.f, 0.f, 0.f, 0.f};
            #pragma unroll
            for (int ks = 0; ks < 8; ++ks) {
                float f0 = W12T[(nt * 8 + gid) * 68 + ks * 8 + tig];
                float f1 = W12T[(nt * 8 + gid) * 68 + ks * 8 + tig + 4];
                uint32_t bh[2], bl[2];
                split3(f0, bh[0], bl[0]);
                split3(f1, bh[1], bl[1]);
                mma168(acc, ahi[ks], bh);
                mma168(acc, ahi[ks], bl);
                mma168(acc, alo[ks], bh);
            }
            int j0 = nt * 8 + 2 * tig;
            float q0 = QC[j0], q1 = QC[j0 + 1];
            float2 r0 = make_float2(fmaxf(acc[0] + q0, 0.f), fmaxf(acc[1] + q1, 0.f));
            float2 r1 = make_float2(fmaxf(acc[2] + q0, 0.f), fmaxf(acc[3] + q1, 0.f));
            *(float2*)(H1 + (mb + gid)     * 68 + j0) = r0;
            *(float2*)(H1 + (mb + gid + 8) * 68 + j0) = r1;
        }
    }
    __syncthreads();

    // ---- GEMM2: scores = reduce_n relu(H1 @ W2T^T + b2)*wo ----
    {
        uint32_t ahi[8][4], alo[8][4];
        #pragma unroll
        for (int ks = 0; ks < 8; ++ks) {
            float r0 = H1[(mb + gid)     * 68 + ks * 8 + tig];
            float r1 = H1[(mb + gid + 8) * 68 + ks * 8 + tig];
            float r2 = H1[(mb + gid)     * 68 + ks * 8 + tig + 4];
            float r3 = H1[(mb + gid + 8) * 68 + ks * 8 + tig + 4];
            split3(r0, ahi[ks][0], alo[ks][0]);
            split3(r1, ahi[ks][1], alo[ks][1]);
            split3(r2, ahi[ks][2], alo[ks][2]);
            split3(r3, ahi[ks][3], alo[ks][3]);
        }
        float srow0 = 0.f, srow8 = 0.f;
        #pragma unroll
        for (int nt = 0; nt < 4; ++nt) {
            float acc[4] = {0.f, 0.f, 0.f, 0.f};
            #pragma unroll
            for (int ks = 0; ks < 8; ++ks) {
                float f0 = W2T[(nt * 8 + gid) * 68 + ks * 8 + tig];
                float f1 = W2T[(nt * 8 + gid) * 68 + ks * 8 + tig + 4];
                uint32_t bh[2], bl[2];
                split3(f0, bh[0], bl[0]);
                split3(f1, bh[1], bl[1]);
                mma168(acc, ahi[ks], bh);
                mma168(acc, ahi[ks], bl);
                mma168(acc, alo[ks], bh);
            }
            int n0 = nt * 8 + 2 * tig;
            float bb0 = B2S[n0], bb1 = B2S[n0 + 1];
            float w0 = WOS[n0],  w1v = WOS[n0 + 1];
            srow0 += fmaxf(acc[0] + bb0, 0.f) * w0 + fmaxf(acc[1] + bb1, 0.f) * w1v;
            srow8 += fmaxf(acc[2] + bb0, 0.f) * w0 + fmaxf(acc[3] + bb1, 0.f) * w1v;
        }
        // reduce across the 4 lanes of each row group (tig dimension)
        srow0 += __shfl_xor_sync(0xffffffffu, srow0, 1);
        srow0 += __shfl_xor_sync(0xffffffffu, srow0, 2);
        srow8 += __shfl_xor_sync(0xffffffffu, srow8, 1);
        srow8 += __shfl_xor_sync(0xffffffffu, srow8, 2);

        if (tig == 0) {
            float bos = bo[0];
            int tg0 = t0 + mb + gid;
            int tg8 = tg0 + 8;
            if (tg0 < T_LEN)
                g_scores[b * TPAD + tg0] = mask[b * T_LEN + tg0] ? srow0 + bos : -1e9f;
            else if (tg0 < TPAD)
                g_scores[b * TPAD + tg0] = -1e9f;
            if (tg8 < T_LEN)
                g_scores[b * TPAD + tg8] = mask[b * T_LEN + tg8] ? srow8 + bos : -1e9f;
            else if (tg8 < TPAD)
                g_scores[b * TPAD + tg8] = -1e9f;
        }
    }
}

// ---------------------------------------------------------------------------
// Kernel B: softmax over 224 scores + interest vector (re-gather keys).
// ---------------------------------------------------------------------------
__global__ void __launch_bounds__(256, 8)
din_softmax_kernel(const int* __restrict__ hist,
                   const float* __restrict__ item_table)
{
    __shared__ float SC[TPAD];
    __shared__ float WG[TPAD];
    __shared__ float RED[8];
    __shared__ float SV[2];

    const int b    = blockIdx.x;
    const int tid  = threadIdx.x;
    const int lane = tid & 31;
    const int warp = tid >> 5;

    float s = (tid < TPAD) ? g_scores[b * TPAD + tid] : -3.4e38f;
    if (tid < TPAD) SC[tid] = s;

    float m = s;
    #pragma unroll
    for (int off = 16; off > 0; off >>= 1)
        m = fmaxf(m, __shfl_xor_sync(0xffffffffu, m, off));
    if (lane == 0) RED[warp] = m;
    __syncthreads();
    if (warp == 0) {
        float mm = (lane < 7) ? RED[lane] : -3.4e38f;
        #pragma unroll
        for (int off = 4; off > 0; off >>= 1)
            mm = fmaxf(mm, __shfl_xor_sync(0xffffffffu, mm, off));
        if (lane == 0) SV[0] = mm;
    }
    __syncthreads();

    float e = 0.f;
    if (tid < TPAD) {
        e = expf(SC[tid] - SV[0]);
        WG[tid] = e;
    }
    #pragma unroll
    for (int off = 16; off > 0; off >>= 1)
        e += __shfl_xor_sync(0xffffffffu, e, off);
    if (lane == 0) RED[warp] = e;
    __syncthreads();
    if (warp == 0) {
        float t2 = (lane < 7) ? RED[lane] : 0.f;
        #pragma unroll
        for (int off = 4; off > 0; off >>= 1)
            t2 += __shfl_xor_sync(0xffffffffu, t2, off);
        if (lane == 0) SV[1] = t2;
    }
    __syncthreads();

    const int e0 = warp * 8;
    float a0=0.f,a1=0.f,a2=0.f,a3=0.f,a4=0.f,a5=0.f,a6=0.f,a7=0.f;
    #pragma unroll
    for (int i = 0; i < 7; ++i) {
        int t = lane + 32 * i;
        float wv = WG[t];
        if (t < T_LEN) {
            int row = hist[b * T_LEN + t];
            const float* kp = item_table + (long)row * E_DIM + e0;
            float4 va = *(const float4*)(kp);
            float4 vb = *(const float4*)(kp + 4);
            a0 += wv * va.x; a1 += wv * va.y; a2 += wv * va.z; a3 += wv * va.w;
            a4 += wv * vb.x; a5 += wv * vb.y; a6 += wv * vb.z; a7 += wv * vb.w;
        }
    }
    #pragma unroll
    for (int off = 16; off > 0; off >>= 1) {
        a0 += __shfl_xor_sync(0xffffffffu, a0, off);
        a1 += __shfl_xor_sync(0xffffffffu, a1, off);
        a2 += __shfl_xor_sync(0xffffffffu, a2, off);
        a3 += __shfl_xor_sync(0xffffffffu, a3, off);
        a4 += __shfl_xor_sync(0xffffffffu, a4, off);
        a5 += __shfl_xor_sync(0xffffffffu, a5, off);
        a6 += __shfl_xor_sync(0xffffffffu, a6, off);
        a7 += __shfl_xor_sync(0xffffffffu, a7, off);
    }
    if (lane == 0) {
        float invs = 1.0f / SV[1];
        float* gi = g_interest + (long)b * E_DIM + e0;
        gi[0]=a0*invs; gi[1]=a1*invs; gi[2]=a2*invs; gi[3]=a3*invs;
        gi[4]=a4*invs; gi[5]=a5*invs; gi[6]=a6*invs; gi[7]=a7*invs;
    }
}

// ---------------------------------------------------------------------------
// Kernel C: final MLP, 8 rows/CTA, 512 threads, K-split partials.
// ---------------------------------------------------------------------------
#define BTILE 8
#define C_AT   0
#define C_P    2176
#define C_H1   (2176 + 5120)
#define C_Q    (2176 + 5120 + 3072)
#define C_R    (2176 + 5120 + 3072 + 5120)
#define SMEMC_BYTES ((2176 + 5120 + 3072 + 5120 + 32) * 4)

__global__ void __launch_bounds__(512, 2)
din_mlp_kernel(const int* __restrict__ tgt,
               const int* __restrict__ sf,
               const float* __restrict__ dense,
               const float* __restrict__ item_table,
               const float* __restrict__ user_table,
               const float* __restrict__ ctx_table,
               const float* __restrict__ w1, const float* __restrict__ b1,
               const float* __restrict__ w2, const float* __restrict__ b2,
               const float* __restrict__ ow, const float* __restrict__ ob,
               float* __restrict__ out)
{
    extern __shared__ float smc[];
    float* At  = smc + C_AT;
    float* P   = smc + C_P;
    float* H1t = smc + C_H1;
    float* Qp  = smc + C_Q;
    float* R   = smc + C_R;

    const int b0   = blockIdx.x * BTILE;
    const int tid  = threadIdx.x;
    const int lane = tid & 31;

    for (int i = tid; i < 272 * BTILE; i += 512) {
        int bb = i & (BTILE - 1);
        int k  = i / BTILE;
        int gb = b0 + bb;
        float v;
        if (k < 64)        v = user_table[(long)sf[gb * 2] * 64 + k];
        else if (k < 128)  v = ctx_table[(long)sf[gb * 2 + 1] * 64 + (k - 64)];
        else if (k < 192)  v = item_table[(long)tgt[gb] * 64 + (k - 128)];
        else if (k < 256)  v = g_interest[(long)gb * 64 + (k - 192)];
        else               v = dense[gb * 16 + (k - 256)];
        At[k * BTILE + bb] = v;
    }
    __syncthreads();

    {
        const int n  = tid & 255;
        const int ks = tid >> 8;
        const int k0 = ks * 136;
        float2 acc[4];
        #pragma unroll
        for (int p = 0; p < 4; ++p) acc[p] = make_float2(0.f, 0.f);
        #pragma unroll 4
        for (int k = k0; k < k0 + 136; ++k) {
            float wv = w1[k * 256 + n];
            float2 bb = make_float2(wv, wv);
            const float4* ar4 = (const float4*)(At + k * BTILE);
            float4 aA = ar4[0];
            float4 aB = ar4[1];
            acc[0] = fma2(make_float2(aA.x, aA.y), bb, acc[0]);
            acc[1] = fma2(make_float2(aA.z, aA.w), bb, acc[1]);
            acc[2] = fma2(make_float2(aB.x, aB.y), bb, acc[2]);
            acc[3] = fma2(make_float2(aB.z, aB.w), bb, acc[3]);
        }
        float* pr = P + tid * 10;
        #pragma unroll
        for (int p = 0; p < 4; ++p) *(float2*)(pr + 2 * p) = acc[p];
    }
    __syncthreads();

    if (tid < 256) {
        float bias = b1[tid];
        const float* p0 = P + tid * 10;
        const float* p1 = P + (tid + 256) * 10;
        #pragma unroll
        for (int p = 0; p < 4; ++p) {
            float2 x = *(const float2*)(p0 + 2 * p);
            float2 y = *(const float2*)(p1 + 2 * p);
            float2 r = make_float2(fmaxf(x.x + y.x + bias, 0.f),
                                   fmaxf(x.y + y.y + bias, 0.f));
            *(float2*)(H1t + tid * 12 + 2 * p) = r;
        }
    }
    __syncthreads();

    {
        const int n  = tid & 127;
        const int ks = tid >> 7;
        const int k0 = ks * 64;
        float2 acc[4];
        #pragma unroll
        for (int p = 0; p < 4; ++p) acc[p] = make_float2(0.f, 0.f);
        #pragma unroll 4
        for (int k = k0; k < k0 + 64; ++k) {
            float wv = w2[k * 128 + n];
            float2 bb = make_float2(wv, wv);
            const float4* hr4 = (const float4*)(H1t + k * 12);
            float4 aA = hr4[0];
            float4 aB = hr4[1];
            acc[0] = fma2(make_float2(aA.x, aA.y), bb, acc[0]);
            acc[1] = fma2(make_float2(aA.z, aA.w), bb, acc[1]);
            acc[2] = fma2(make_float2(aB.x, aB.y), bb, acc[2]);
            acc[3] = fma2(make_float2(aB.z, aB.w), bb, acc[3]);
        }
        float* qr = Qp + tid * 10;
        #pragma unroll
        for (int p = 0; p < 4; ++p) *(float2*)(qr + 2 * p) = acc[p];
    }
    __syncthreads();

    if (tid < 128) {
        const int n = tid;
        float bias = b2[n];
        float owl  = ow[n];
        float s[8];
        #pragma unroll
        for (int m = 0; m < 8; ++m) {
            float v = Qp[(n)       * 10 + m]
                    + Qp[(n + 128) * 10 + m]
                    + Qp[(n + 256) * 10 + m]
                    + Qp[(n + 384) * 10 + m];
            s[m] = fmaxf(v + bias, 0.f) * owl;
        }
        #pragma unroll
        for (int off = 16; off > 0; off >>= 1) {
            #pragma unroll
            for (int m = 0; m < 8; ++m)
                s[m] += __shfl_xor_sync(0xffffffffu, s[m], off);
        }
        if (lane == 0) {
            int w = tid >> 5;
            #pragma unroll
            for (int m = 0; m < 8; ++m) R[w * 8 + m] = s[m];
        }
    }
    __syncthreads();
    if (tid < BTILE) {
        float s = R[tid] + R[8 + tid] + R[16 + tid] + R[24 + tid] + ob[0];
        out[b0 + tid] = s;
    }
}

// ---------------------------------------------------------------------------
extern "C" void kernel_launch(void* const* d_in, const int* in_sizes, int n_in,
                              void* d_out, int out_size)
{
    const int*   tgt   = (const int*)d_in[0];
    const int*   hist  = (const int*)d_in[1];
    const int*   mask  = (const int*)d_in[2];
    const int*   sf    = (const int*)d_in[3];
    const float* dense = (const float*)d_in[4];
    const float* item_table = (const float*)d_in[5];
    const float* user_table = (const float*)d_in[6];
    const float* ctx_table  = (const float*)d_in[7];
    const float* att_w1 = (const float*)d_in[8];
    const float* att_b1 = (const float*)d_in[9];
    const float* att_w2 = (const float*)d_in[10];
    const float* att_b2 = (const float*)d_in[11];
    const float* att_wo = (const float*)d_in[12];
    const float* att_bo = (const float*)d_in[13];
    const float* mlp_w1 = (const float*)d_in[14];
    const float* mlp_b1 = (const float*)d_in[15];
    const float* mlp_w2 = (const float*)d_in[16];
    const float* mlp_b2 = (const float*)d_in[17];
    const float* out_w  = (const float*)d_in[18];
    const float* out_b  = (const float*)d_in[19];
    float*       out    = (float*)d_out;

    cudaFuncSetAttribute(din_scores_kernel, cudaFuncAttributeMaxDynamicSharedMemorySize, SMEMA_BYTES);
    cudaFuncSetAttribute(din_mlp_kernel,    cudaFuncAttributeMaxDynamicSharedMemorySize, SMEMC_BYTES);

    din_fold_kernel<<<B_ROWS, 256>>>(tgt, item_table, att_w1, att_b1);

    din_scores_kernel<<<B_ROWS * 2, 256, SMEMA_BYTES>>>(
        tgt, hist, mask, item_table, att_w2, att_b2, att_wo, att_bo);

    din_softmax_kernel<<<B_ROWS, 256>>>(hist, item_table);

    din_mlp_kernel<<<B_ROWS / BTILE, 512, SMEMC_BYTES>>>(
        tgt, sf, dense, item_table, user_table, ctx_table,
        mlp_w1, mlp_b1, mlp_w2, mlp_b2, out_w, out_b, out);
}